// round 14
// baseline (speedup 1.0000x reference)
#include <cuda_runtime.h>

#define T_LEN 5000
#define HID   64
#define BATCH 256

typedef unsigned long long u64t;

// ---- packed f32x2 helpers ----
__device__ __forceinline__ u64t pack2(float lo, float hi) {
    u64t d;
    asm("mov.b64 %0, {%1, %2};" : "=l"(d) : "f"(lo), "f"(hi));
    return d;
}
__device__ __forceinline__ void unpack2(u64t v, float& lo, float& hi) {
    asm("mov.b64 {%0, %1}, %2;" : "=f"(lo), "=f"(hi) : "l"(v));
}
__device__ __forceinline__ u64t ffma2(u64t a, u64t b, u64t c) {
    u64t d;
    asm("fma.rn.f32x2 %0, %1, %2, %3;" : "=l"(d) : "l"(a), "l"(b), "l"(c));
    return d;
}
__device__ __forceinline__ u64t add2(u64t a, u64t b) {
    u64t d;
    asm("add.rn.f32x2 %0, %1, %2;" : "=l"(d) : "l"(a), "l"(b));
    return d;
}

// ---- hardware tanh (sm_75+): single MUFU op ----
__device__ __forceinline__ float tanh_hw(float x) {
    float r;
    asm("tanh.approx.f32 %0, %1;" : "=f"(r) : "f"(x));
    return r;
}
// sigmoid(x) = 0.5*tanh(0.5x) + 0.5
__device__ __forceinline__ float sigmoid_hw(float x) {
    return fmaf(0.5f, tanh_hw(0.5f * x), 0.5f);
}

__global__ __launch_bounds__(128, 2)
void lstm_fused_kernel(const float* __restrict__ x,
                       const float* __restrict__ W_ih,
                       const float* __restrict__ W_hh,
                       const float* __restrict__ b_ih,
                       const float* __restrict__ b_hh,
                       const float* __restrict__ W_fc,
                       const float* __restrict__ b_fc,
                       float* __restrict__ out)
{
    __shared__ __align__(16) float x_sh[T_LEN];   // whole input row (20 KB)
    __shared__ __align__(16) float h_sh[HID];     // hidden state

    const int tid = threadIdx.x;
    const int row = blockIdx.x;

    // ---- stage the full x row into SMEM, coalesced float4 ----
    {
        const float4* xr = reinterpret_cast<const float4*>(x + row * T_LEN);
        float4* xs = reinterpret_cast<float4*>(x_sh);
        for (int i = tid; i < T_LEN / 4; i += 128) xs[i] = xr[i];
    }

    // ---- thread = (unit u, gate-pair p): p=0 -> (i,f), p=1 -> (g,o),
    //      FULL K=64 per thread; partner = lane^1, same warp ----
    const int u = tid >> 1;
    const int p = tid & 1;
    const int gA = 2 * p;            // gate index of first owned gate
    const int gB = 2 * p + 1;
    const int rA = gA * HID + u;     // W_hh row / bias index, gate A
    const int rB = gB * HID + u;

    // ---- weights: 2 gate rows x 32 k-pairs -> 64 u64-halves = 64 regs ----
    u64t wA[32], wB[32];
    {
        const float4* ra = reinterpret_cast<const float4*>(W_hh + rA * HID);
        const float4* rb = reinterpret_cast<const float4*>(W_hh + rB * HID);
        #pragma unroll
        for (int i = 0; i < HID / 4; i++) {
            float4 a = ra[i], b = rb[i];
            wA[2 * i + 0] = pack2(a.x, a.y);
            wA[2 * i + 1] = pack2(a.z, a.w);
            wB[2 * i + 0] = pack2(b.x, b.y);
            wB[2 * i + 1] = pack2(b.z, b.w);
        }
    }
    // full bias + x weight per owned gate (preacts are complete in-thread)
    const u64t wihA2 = pack2(W_ih[rA], 0.0f);
    const u64t wihB2 = pack2(W_ih[rB], 0.0f);
    const u64t bA2   = pack2(b_ih[rA] + b_hh[rA], 0.0f);
    const u64t bB2   = pack2(b_ih[rB] + b_hh[rB], 0.0f);

    if (tid < HID) h_sh[tid] = 0.0f;
    float c = 0.0f;                  // redundant in both partner lanes
    __syncthreads();

    // ---- phase-skew: odd blocks delay ~half a step so co-resident CTAs
    //      interleave FMA phase with tail phase instead of phase-locking ----
    if (blockIdx.x & 1) {
        float d = 1.0f;
        #pragma unroll
        for (int i = 0; i < 64; i++) {
            d = fmaf(d, 1.0000001f, 1e-20f);
            asm volatile("" : "+f"(d));
        }
    }

    const ulonglong2* hp = reinterpret_cast<const ulonglong2*>(h_sh);

    // ================= recurrence: 5000 serial steps =================
    for (int t = 0; t < T_LEN; t++) {
        const float xv = x_sh[t];
        const u64t x2 = pack2(xv, xv);

        // 4 chains (2 per gate) x 16 deep
        u64t a0 = ffma2(x2, wihA2, bA2);
        u64t a1 = 0ULL;
        u64t b0 = ffma2(x2, wihB2, bB2);
        u64t b1 = 0ULL;

        #pragma unroll
        for (int j = 0; j < 16; j++) {
            ulonglong2 hv = hp[j];   // 4 h values (warp-uniform -> broadcast)
            a0 = ffma2(hv.x, wA[2 * j + 0], a0);
            a1 = ffma2(hv.y, wA[2 * j + 1], a1);
            b0 = ffma2(hv.x, wB[2 * j + 0], b0);
            b1 = ffma2(hv.y, wB[2 * j + 1], b1);
        }
        u64t sa = add2(a0, a1);
        u64t sb = add2(b0, b1);
        float l, h2;
        unpack2(sa, l, h2); const float preA = l + h2;   // complete preact
        unpack2(sb, l, h2); const float preB = l + h2;

        // activations for the 2 owned gates (partner computes the other 2
        // in parallel BEFORE the exchange)
        float m0, m1;
        if (p == 0) { m0 = sigmoid_hw(preA); m1 = sigmoid_hw(preB); } // i, f
        else        { m0 = tanh_hw(preA);    m1 = sigmoid_hw(preB); } // g, o

        // exchange activated pair with the partner lane (2 SHFLs)
        const float o0 = __shfl_xor_sync(0xffffffffu, m0, 1);
        const float o1 = __shfl_xor_sync(0xffffffffu, m1, 1);

        const float iv = p ? o0 : m0;
        const float fv = p ? o1 : m1;
        const float gv = p ? m0 : o0;
        const float ov = p ? m1 : o1;

        // state update, redundant in both lanes (exact copies -> bit-equal)
        c = fmaf(fv, c, iv * gv);
        const float hval = ov * tanh_hw(c);

        if (!p) h_sh[u] = hval;      // one writer per unit
        __syncthreads();             // single barrier per step
    }

    // ================= FC(64 -> 128) + ReLU epilogue =================
    {
        const float4* wr = reinterpret_cast<const float4*>(W_fc + tid * HID);
        float acc = b_fc[tid];
        #pragma unroll
        for (int i = 0; i < HID / 4; i++) {
            float4 w = wr[i];
            acc += h_sh[4 * i + 0] * w.x;
            acc += h_sh[4 * i + 1] * w.y;
            acc += h_sh[4 * i + 2] * w.z;
            acc += h_sh[4 * i + 3] * w.w;
        }
        out[row * 128 + tid] = fmaxf(acc, 0.0f);
    }
}

extern "C" void kernel_launch(void* const* d_in, const int* in_sizes, int n_in,
                              void* d_out, int out_size)
{
    const float* x    = (const float*)d_in[0];
    const float* W_ih = (const float*)d_in[1];
    const float* W_hh = (const float*)d_in[2];
    const float* b_ih = (const float*)d_in[3];
    const float* b_hh = (const float*)d_in[4];
    const float* W_fc = (const float*)d_in[5];
    const float* b_fc = (const float*)d_in[6];

    lstm_fused_kernel<<<BATCH, 128>>>(x, W_ih, W_hh, b_ih, b_hh,
                                      W_fc, b_fc, (float*)d_out);
}

// round 17
// speedup vs baseline: 1.2036x; 1.2036x over previous
#include <cuda_runtime.h>

#define T_LEN 5000
#define HID   64
#define BATCH 256

typedef unsigned long long u64t;

// ---- packed f32x2 helpers ----
__device__ __forceinline__ u64t pack2(float lo, float hi) {
    u64t d;
    asm("mov.b64 %0, {%1, %2};" : "=l"(d) : "f"(lo), "f"(hi));
    return d;
}
__device__ __forceinline__ void unpack2(u64t v, float& lo, float& hi) {
    asm("mov.b64 {%0, %1}, %2;" : "=f"(lo), "=f"(hi) : "l"(v));
}
__device__ __forceinline__ u64t ffma2(u64t a, u64t b, u64t c) {
    u64t d;
    asm("fma.rn.f32x2 %0, %1, %2, %3;" : "=l"(d) : "l"(a), "l"(b), "l"(c));
    return d;
}
__device__ __forceinline__ u64t add2(u64t a, u64t b) {
    u64t d;
    asm("add.rn.f32x2 %0, %1, %2;" : "=l"(d) : "l"(a), "l"(b));
    return d;
}

// ---- hardware tanh (sm_75+): single MUFU op ----
__device__ __forceinline__ float tanh_hw(float x) {
    float r;
    asm("tanh.approx.f32 %0, %1;" : "=f"(r) : "f"(x));
    return r;
}

__global__ __launch_bounds__(256, 2)
void lstm_fused_kernel(const float* __restrict__ x,
                       const float* __restrict__ W_ih,
                       const float* __restrict__ W_hh,
                       const float* __restrict__ b_ih,
                       const float* __restrict__ b_hh,
                       const float* __restrict__ W_fc,
                       const float* __restrict__ b_fc,
                       float* __restrict__ out)
{
    __shared__ __align__(16) float x_sh[T_LEN];   // whole input row (20 KB)
    __shared__ __align__(16) float h_sh[HID];     // hidden state

    const int tid = threadIdx.x;
    const int row = blockIdx.x;

    // ---- stage the full x row into SMEM, coalesced float4 ----
    {
        const float4* xr = reinterpret_cast<const float4*>(x + row * T_LEN);
        float4* xs = reinterpret_cast<float4*>(x_sh);
        for (int i = tid; i < T_LEN / 4; i += 256) xs[i] = xr[i];
    }

    // ---- thread = (unit u, gate g), FULL K=64; the 4 gates of unit u are
    //      lanes (4u..4u+3) of the same warp ----
    const int u = tid >> 2;          // unit 0..63
    const int g = tid & 3;           // 0:i 1:f 2:g 3:o
    const int r = g * HID + u;       // W_hh row / bias index

    // ---- weights: one full gate row -> 32 u64 regs (64 registers) ----
    u64t w2[32];
    {
        const float4* wr = reinterpret_cast<const float4*>(W_hh + r * HID);
        #pragma unroll
        for (int i = 0; i < HID / 4; i++) {
            float4 v = wr[i];
            w2[2 * i + 0] = pack2(v.x, v.y);
            w2[2 * i + 1] = pack2(v.z, v.w);
        }
    }
    const float wih  = W_ih[r];
    const float bias = b_ih[r] + b_hh[r];

    // divergence-free activation: act = A*tanh_hw(B*pre) + C
    //   sigmoid: A=B=C=0.5   tanh (g==2): A=B=1, C=0
    const float Aact = (g == 2) ? 1.0f : 0.5f;
    const float Cact = (g == 2) ? 0.0f : 0.5f;

    if (tid < HID) h_sh[tid] = 0.0f;
    float c = 0.0f;                  // redundant in all 4 lanes of unit u
    __syncthreads();

    // ---- phase-skew: odd blocks delay so co-resident CTAs interleave
    //      FMA phase with tail phase instead of phase-locking ----
    if (blockIdx.x & 1) {
        float d = 1.0f;
        #pragma unroll
        for (int i = 0; i < 64; i++) {
            d = fmaf(d, 1.0000001f, 1e-20f);
            asm volatile("" : "+f"(d));
        }
    }

    const ulonglong2* hp = reinterpret_cast<const ulonglong2*>(h_sh);

    // ================= recurrence: 5000 serial steps =================
    for (int t = 0; t < T_LEN; t++) {
        // x-term + bias folded into chain init
        const float head = fmaf(x_sh[t], wih, bias);
        u64t a0 = pack2(head, 0.0f);
        u64t a1 = 0ULL;

        #pragma unroll
        for (int j = 0; j < 8; j++) {           // 16 LDS.128 (broadcast), 32 FFMA2
            ulonglong2 hv0 = hp[2 * j];
            ulonglong2 hv1 = hp[2 * j + 1];
            a0 = ffma2(hv0.x, w2[4 * j + 0], a0);
            a1 = ffma2(hv0.y, w2[4 * j + 1], a1);
            a0 = ffma2(hv1.x, w2[4 * j + 2], a0);
            a1 = ffma2(hv1.y, w2[4 * j + 3], a1);
        }
        u64t s = add2(a0, a1);
        float l, h2;
        unpack2(s, l, h2);
        const float pre = l + h2;               // complete preact, in-thread

        // activation (uniform path; MUFU spread across the 4 gate lanes)
        const float act = fmaf(Aact, tanh_hw(Aact * pre), Cact);

        // gather the 4 activations within the gate group (lanes 4u..4u+3)
        const float b   = __shfl_xor_sync(0xffffffffu, act, 1);
        const float lo_pair = (g & 1) ? b   : act;   // gate (g&2)+0
        const float hi_pair = (g & 1) ? act : b;     // gate (g&2)+1
        const float lo_o = __shfl_xor_sync(0xffffffffu, lo_pair, 2);
        const float hi_o = __shfl_xor_sync(0xffffffffu, hi_pair, 2);

        const bool up = (g & 2);
        const float iv = up ? lo_o    : lo_pair;
        const float fv = up ? hi_o    : hi_pair;
        const float gv = up ? lo_pair : lo_o;
        const float ov = up ? hi_pair : hi_o;

        // state update — identical in all 4 lanes (exact copies via shfl)
        c = fmaf(fv, c, iv * gv);
        const float hval = ov * tanh_hw(c);

        if (g == 0) h_sh[u] = hval;  // one writer per unit
        __syncthreads();             // single barrier per step
    }

    // ================= FC(64 -> 128) + ReLU epilogue =================
    if (tid < 128) {
        const float4* wr = reinterpret_cast<const float4*>(W_fc + tid * HID);
        float acc = b_fc[tid];
        #pragma unroll
        for (int i = 0; i < HID / 4; i++) {
            float4 w = wr[i];
            acc += h_sh[4 * i + 0] * w.x;
            acc += h_sh[4 * i + 1] * w.y;
            acc += h_sh[4 * i + 2] * w.z;
            acc += h_sh[4 * i + 3] * w.w;
        }
        out[row * 128 + tid] = fmaxf(acc, 0.0f);
    }
}

extern "C" void kernel_launch(void* const* d_in, const int* in_sizes, int n_in,
                              void* d_out, int out_size)
{
    const float* x    = (const float*)d_in[0];
    const float* W_ih = (const float*)d_in[1];
    const float* W_hh = (const float*)d_in[2];
    const float* b_ih = (const float*)d_in[3];
    const float* b_hh = (const float*)d_in[4];
    const float* W_fc = (const float*)d_in[5];
    const float* b_fc = (const float*)d_in[6];

    lstm_fused_kernel<<<BATCH, 256>>>(x, W_ih, W_hh, b_ih, b_hh,
                                      W_fc, b_fc, (float*)d_out);
}